// round 14
// baseline (speedup 1.0000x reference)
#include <cuda_runtime.h>
#include <cuda_fp16.h>
#include <cstdint>

// GGNN message passing (SIMT mma.sync; tcgen05 unavailable on sm_103 target).
// Stage1 (tf32 MMA): G[j,dir,c,d] = sum_e h[j,e]*W[dir,c,d,e]; fp16x2 blob
//   [b][dir][ch][r][pd]: ch=j>>4, r = 8*((j&15)>>2) + ((j&15)&3) + 4a (a=classpair),
//   word = (G_{c=2a}[d], G_{c=2a+1}[d]), pd = (d&7)*8+(d>>3).
// Stage2 (fp16 m16n8k16): out[b,i,dir*64+d] = sum_{j,c} 1[adjX==c]*G + bias.
//   K-map: f16x2 row m -> (jj=m&3, a=m>>2); one adj value + one u64 shift gives
//   both classpair words (exact one-hot). Warp covers 64 rows (4 row-blocks);
//   block = 4 warps = 256 rows = 2 mtiles, amortizing B LDS across 2x MMAs.
//   dir=0: adjX=adj[b,i,j]; dir=1: adjX=adj[b,j,i].

__device__ uint32_t g_scratch[(size_t)8388608];  // 32 MB blob (f16x2 words)

__device__ __forceinline__ uint32_t f2tf(float x) {
    uint32_t r; asm("cvt.rna.tf32.f32 %0, %1;" : "=r"(r) : "f"(x)); return r;
}
__device__ __forceinline__ uint32_t pkh2(float lo, float hi) {
    __half2 p = __floats2half2_rn(lo, hi); return *(uint32_t*)&p;
}
__device__ __forceinline__ void mma8_tf32(float* d, uint32_t a0, uint32_t a1,
                                          uint32_t a2, uint32_t a3, uint32_t b0, uint32_t b1) {
    asm volatile("mma.sync.aligned.m16n8k8.row.col.f32.tf32.tf32.f32 "
                 "{%0,%1,%2,%3}, {%4,%5,%6,%7}, {%8,%9}, {%0,%1,%2,%3};"
                 : "+f"(d[0]), "+f"(d[1]), "+f"(d[2]), "+f"(d[3])
                 : "r"(a0), "r"(a1), "r"(a2), "r"(a3), "r"(b0), "r"(b1));
}
__device__ __forceinline__ void mma16_f16(float* d, uint32_t a0, uint32_t a1,
                                          uint32_t a2, uint32_t a3, uint32_t b0, uint32_t b1) {
    asm volatile("mma.sync.aligned.m16n8k16.row.col.f32.f16.f16.f32 "
                 "{%0,%1,%2,%3}, {%4,%5,%6,%7}, {%8,%9}, {%0,%1,%2,%3};"
                 : "+f"(d[0]), "+f"(d[1]), "+f"(d[2]), "+f"(d[3])
                 : "r"(a0), "r"(a1), "r"(a2), "r"(a3), "r"(b0), "r"(b1));
}
__device__ __forceinline__ void cpa16(uint32_t daddr, const void* gaddr) {
    asm volatile("cp.async.cg.shared.global [%0], [%1], 16;" :: "r"(daddr), "l"(gaddr));
}
__device__ __forceinline__ void cpa_commit() {
    asm volatile("cp.async.commit_group;" ::: "memory");
}
template <int N>
__device__ __forceinline__ void cpa_wait() {
    asm volatile("cp.async.wait_group %0;" :: "n"(N) : "memory");
}

// ---------------------------------------------------------------------------
// Stage 1: grid 2048 = (512 mtiles x 4 p4), 128 thr.
// smem: hs[64*68] + ws[64*136] = 13056 words = 52.2 KB.
// ---------------------------------------------------------------------------
#define S1_SMEM_W (4352 + 8704)

__global__ __launch_bounds__(128) void ggnn_stage1(const float* __restrict__ h,
                                                   const float* __restrict__ Win,
                                                   const float* __restrict__ Wout) {
    extern __shared__ uint32_t s1[];
    uint32_t* hs = s1;            // [row][e] stride 68
    uint32_t* ws = s1 + 4352;     // [e][n] stride 136

    const int bx = blockIdx.x;
    const int mtile = bx >> 2, p4 = bx & 3;
    const int t = threadIdx.x;
    const int warp = t >> 5, lane = t & 31;
    const int g = lane >> 2, tig = lane & 3;
    const int r0 = warp * 16 + g;

    {
        const float* Wd = (p4 & 2) ? Wout : Win;
        const float4* src = (const float4*)(Wd + (size_t)(p4 & 1) * 8192
                                            + (t >> 6) * 4096 + (t & 63) * 64);
#pragma unroll
        for (int i = 0; i < 16; i++) {
            float4 v = src[i];
            int e = 4 * i;
            ws[(e + 0) * 136 + t] = f2tf(v.x);
            ws[(e + 1) * 136 + t] = f2tf(v.y);
            ws[(e + 2) * 136 + t] = f2tf(v.z);
            ws[(e + 3) * 136 + t] = f2tf(v.w);
        }
    }
    const float* hbase = h + (size_t)mtile * 4096;
#pragma unroll
    for (int q = 0; q < 8; q++) {
        int f4 = t + q * 128;
        int row = f4 >> 4, e4 = (f4 & 15) * 4;
        float4 v = *(const float4*)(hbase + row * 64 + e4);
        uint4 u = make_uint4(f2tf(v.x), f2tf(v.y), f2tf(v.z), f2tf(v.w));
        *(uint4*)(hs + row * 68 + e4) = u;
    }
    __syncthreads();

    float acc[16][4];
#pragma unroll
    for (int nt = 0; nt < 16; nt++)
#pragma unroll
        for (int k = 0; k < 4; k++) acc[nt][k] = 0.f;

#pragma unroll
    for (int ks = 0; ks < 8; ks++) {
        int e0 = ks * 8;
        uint32_t a0 = hs[r0 * 68 + e0 + tig];
        uint32_t a1 = hs[(r0 + 8) * 68 + e0 + tig];
        uint32_t a2 = hs[r0 * 68 + e0 + tig + 4];
        uint32_t a3 = hs[(r0 + 8) * 68 + e0 + tig + 4];
#pragma unroll
        for (int nt = 0; nt < 16; nt++) {
            uint32_t b0 = ws[(e0 + tig) * 136 + nt * 8 + g];
            uint32_t b1 = ws[(e0 + tig + 4) * 136 + nt * 8 + g];
            mma8_tf32(acc[nt], a0, a1, a2, a3, b0, b1);
        }
    }

    const int b = mtile >> 4;
    const int ch = (mtile & 15) * 4 + warp;
    const int dir = p4 >> 1, a = p4 & 1;
    uint32_t* blob = g_scratch + ((size_t)(b * 2 + dir) << 17);
#pragma unroll
    for (int rb2 = 0; rb2 < 2; rb2++) {
        int r = 8 * (g >> 2) + 16 * rb2 + (g & 3) + 4 * a;
        uint32_t* dst = blob + ch * 2048 + r * 64 + 16 * tig;
        int i0 = rb2 * 2;
#pragma unroll
        for (int half = 0; half < 2; half++) {
#pragma unroll
            for (int grp = 0; grp < 2; grp++) {
                uint4 u;
                u.x = pkh2(acc[grp * 4 + 0][i0 + half], acc[grp * 4 + 8][i0 + half]);
                u.y = pkh2(acc[grp * 4 + 1][i0 + half], acc[grp * 4 + 9][i0 + half]);
                u.z = pkh2(acc[grp * 4 + 2][i0 + half], acc[grp * 4 + 10][i0 + half]);
                u.w = pkh2(acc[grp * 4 + 3][i0 + half], acc[grp * 4 + 11][i0 + half]);
                *(uint4*)(dst + half * 8 + grp * 4) = u;
            }
        }
    }
}

// ---------------------------------------------------------------------------
// Stage 2: grid (4 double-mtiles, 2 dirs, 32 b), 128 thr (4 warps x 64 rows).
// 2 buffers x (gs 32x68 + adj 5120) = 14592 words = 58.4 KB dynamic smem.
// dir0 adj: [r][jj] stride 20, 256 rows; dir1 adj: [jj][r] stride 264, 16 rows.
// ---------------------------------------------------------------------------
#define GS2_W (32 * 68)                  // 2176
#define AS2_W 5120
#define BUF2_W (GS2_W + AS2_W)           // 7296
#define SM2_W (2 * BUF2_W)               // 14592 words = 58368 B

template <int DIR>
__device__ __forceinline__ void stage2_impl(uint32_t* sm,
                                            const int* __restrict__ adj,
                                            const float* __restrict__ bias,
                                            float* __restrict__ out) {
    const int mt2 = blockIdx.x;          // 0..3 (256-row span)
    const int b   = blockIdx.z;
    const int t = threadIdx.x;
    const int warp = t >> 5, lane = t & 31;
    const int g = lane >> 2, tig = lane & 3;
    const int mbase = mt2 * 256;
    const int rw = warp * 64;

    const uint32_t* blob = g_scratch + ((size_t)(b * 2 + DIR) << 17);
    const int* adjb = adj + (size_t)b * 1048576;

    float acc[4][8][4];
#pragma unroll
    for (int rb = 0; rb < 4; rb++)
#pragma unroll
        for (int nt = 0; nt < 8; nt++)
#pragma unroll
            for (int k = 0; k < 4; k++) acc[rb][nt][k] = 0.f;

    auto issue = [&](int ch, int buf) {
        const int j0 = ch * 16;
        uint32_t gdst = (uint32_t)__cvta_generic_to_shared(sm + buf * BUF2_W);
        uint32_t adst = gdst + GS2_W * 4;
        const uint32_t* gsrc = blob + (size_t)ch * 2048;
#pragma unroll
        for (int q = 0; q < 4; q++) {            // 512 u4s of G
            int idx = t + q * 128;
            int kp = idx >> 4, pd4 = (idx & 15) * 4;
            cpa16(gdst + (kp * 68 + pd4) * 4, gsrc + kp * 64 + pd4);
        }
        if constexpr (DIR == 0) {                // [r][jj] stride 20, 256 rows
#pragma unroll
            for (int q = 0; q < 8; q++) {
                int idx = t + q * 128;
                int r = idx >> 2, c4 = (idx & 3) * 4;
                cpa16(adst + (r * 20 + c4) * 4, adjb + (size_t)(mbase + r) * 1024 + j0 + c4);
            }
        } else {                                 // [jj][r] stride 264, 256 cols
#pragma unroll
            for (int q = 0; q < 8; q++) {
                int idx = t + q * 128;
                int jj = idx >> 6, r4 = (idx & 63) * 4;
                cpa16(adst + (jj * 264 + r4) * 4, adjb + (size_t)(j0 + jj) * 1024 + mbase + r4);
            }
        }
        cpa_commit();
    };

    issue(0, 0);

#pragma unroll 1
    for (int ch = 0; ch < 64; ch++) {
        if (ch < 63) { issue(ch + 1, (ch + 1) & 1); cpa_wait<1>(); }
        else         { cpa_wait<0>(); }
        __syncthreads();

        const uint32_t* gs = sm + (ch & 1) * BUF2_W;
        const int* as_ = (const int*)(gs + GS2_W);
        constexpr int RS = DIR ? 1 : 20;
        constexpr int JS = DIR ? 264 : 1;

#pragma unroll
        for (int ks = 0; ks < 4; ks++) {
            const int jj = 4 * ks + tig;         // this thread's single j
            const int base = (rw + g) * RS + jj * JS;
            // one adj value per 8-row step; u64 shift -> both classpair words
            uint32_t alo[8], ahi[8];
#pragma unroll
            for (int s = 0; s < 8; s++) {
                int v = as_[base + 8 * s * RS];
                uint64_t X = 0x3C00ULL << (v << 4);
                alo[s] = (uint32_t)X;
                ahi[s] = (uint32_t)(X >> 32);
            }

            const uint32_t* bp0 = gs + (8 * ks + tig) * 68 + 8 * g;   // a=0 rows
            const uint32_t* bp1 = bp0 + 4 * 68;                       // a=1 rows
            uint4 B0a = *(const uint4*)(bp0);
            uint4 B0b = *(const uint4*)(bp0 + 4);
            uint4 B1a = *(const uint4*)(bp1);
            uint4 B1b = *(const uint4*)(bp1 + 4);

#pragma unroll
            for (int rb = 0; rb < 4; rb++) {
                uint32_t a0 = alo[2 * rb], a1 = alo[2 * rb + 1];
                uint32_t a2 = ahi[2 * rb], a3 = ahi[2 * rb + 1];
                mma16_f16(acc[rb][0], a0, a1, a2, a3, B0a.x, B1a.x);
                mma16_f16(acc[rb][1], a0, a1, a2, a3, B0a.y, B1a.y);
                mma16_f16(acc[rb][2], a0, a1, a2, a3, B0a.z, B1a.z);
                mma16_f16(acc[rb][3], a0, a1, a2, a3, B0a.w, B1a.w);
                mma16_f16(acc[rb][4], a0, a1, a2, a3, B0b.x, B1b.x);
                mma16_f16(acc[rb][5], a0, a1, a2, a3, B0b.y, B1b.y);
                mma16_f16(acc[rb][6], a0, a1, a2, a3, B0b.z, B1b.z);
                mma16_f16(acc[rb][7], a0, a1, a2, a3, B0b.w, B1b.w);
            }
        }
        __syncthreads();
    }

#pragma unroll
    for (int rb = 0; rb < 4; rb++) {
        const int i0 = mbase + rw + rb * 16 + g;
#pragma unroll
        for (int nt = 0; nt < 8; nt++) {
            int n = DIR * 64 + nt * 8 + tig * 2;
            float2 bv = *(const float2*)(bias + n);
            float* o0 = out + ((size_t)b * 1024 + i0) * 128 + n;
            float* o1 = out + ((size_t)b * 1024 + i0 + 8) * 128 + n;
            *(float2*)o0 = make_float2(acc[rb][nt][0] + bv.x, acc[rb][nt][1] + bv.y);
            *(float2*)o1 = make_float2(acc[rb][nt][2] + bv.x, acc[rb][nt][3] + bv.y);
        }
    }
}

__global__ __launch_bounds__(128) void ggnn_stage2(const int* __restrict__ adj,
                                                   const float* __restrict__ bias,
                                                   float* __restrict__ out) {
    extern __shared__ uint32_t sm[];
    if (blockIdx.y == 0) stage2_impl<0>(sm, adj, bias, out);
    else                 stage2_impl<1>(sm, adj, bias, out);
}

extern "C" void kernel_launch(void* const* d_in, const int* in_sizes, int n_in,
                              void* d_out, int out_size) {
    (void)in_sizes; (void)n_in; (void)out_size;
    const float* h    = (const float*)d_in[0];
    const int*   adj  = (const int*)d_in[1];
    const float* Win  = (const float*)d_in[2];
    const float* Wout = (const float*)d_in[3];
    const float* bias = (const float*)d_in[4];
    float* out = (float*)d_out;

    cudaFuncSetAttribute(ggnn_stage1, cudaFuncAttributeMaxDynamicSharedMemorySize,
                         S1_SMEM_W * 4);
    cudaFuncSetAttribute(ggnn_stage2, cudaFuncAttributeMaxDynamicSharedMemorySize,
                         SM2_W * 4);

    ggnn_stage1<<<2048, 128, S1_SMEM_W * 4>>>(h, Win, Wout);
    ggnn_stage2<<<dim3(4, 2, 32), 128, SM2_W * 4>>>(adj, bias, out);
}

// round 15
// speedup vs baseline: 1.0372x; 1.0372x over previous
#include <cuda_runtime.h>
#include <cuda_fp16.h>
#include <cstdint>

// GGNN message passing (SIMT mma.sync).
// Identity: sum_c 1[adj==c] = 1 exactly, so with G'_c=(W_c-W_3)h (c<3), G_3=W_3 h:
//   m = sum_j sum_{c<3} 1[adjX==c]*G'_c[j]  +  sum_j G_3[j]   (rank-1 term R)
// Stage1 (tf32 MMA): per (mtile,p4=dir*2+a) block. a=0: emits blob rows 0..15
//   (pairs (G'_0,G'_1) per j). a=1: computes (G'_2, G_3); shuffle-packs G'_2 into
//   blob rows 16..23 (pairs across j: m<4:(m,m+4); m>=4:(m+4,m+8)); writes G_3
//   to side buffer. pd = (d&7)*8+(d>>3) everywhere.
// g3reduce: R[b,dir,d] = sum_j G_3 (deterministic).
// Stage2 (fp16 m16n8k16): K=3072 in 64 chunks of 48k (3 steps); A one-hot in regs;
//   epilogue adds bias + R.  dir=0: adjX=adj[b,i,j]; dir=1: adjX=adj[b,j,i].

__device__ uint32_t g_scratch[(size_t)6291456];  // 24 MB blob: [b2][ch][24][64]
__device__ uint32_t g_g3[(size_t)2097152];       // 8 MB: [b2][j][dw'=8tig+nt]
__device__ float    g_R[4096];                   // [b2][64]

__device__ __forceinline__ uint32_t f2tf(float x) {
    uint32_t r; asm("cvt.rna.tf32.f32 %0, %1;" : "=r"(r) : "f"(x)); return r;
}
__device__ __forceinline__ uint32_t pkh2(float lo, float hi) {
    __half2 p = __floats2half2_rn(lo, hi); return *(uint32_t*)&p;
}
__device__ __forceinline__ void mma8_tf32(float* d, uint32_t a0, uint32_t a1,
                                          uint32_t a2, uint32_t a3, uint32_t b0, uint32_t b1) {
    asm volatile("mma.sync.aligned.m16n8k8.row.col.f32.tf32.tf32.f32 "
                 "{%0,%1,%2,%3}, {%4,%5,%6,%7}, {%8,%9}, {%0,%1,%2,%3};"
                 : "+f"(d[0]), "+f"(d[1]), "+f"(d[2]), "+f"(d[3])
                 : "r"(a0), "r"(a1), "r"(a2), "r"(a3), "r"(b0), "r"(b1));
}
__device__ __forceinline__ void mma16_f16(float* d, uint32_t a0, uint32_t a1,
                                          uint32_t a2, uint32_t a3, uint32_t b0, uint32_t b1) {
    asm volatile("mma.sync.aligned.m16n8k16.row.col.f32.f16.f16.f32 "
                 "{%0,%1,%2,%3}, {%4,%5,%6,%7}, {%8,%9}, {%0,%1,%2,%3};"
                 : "+f"(d[0]), "+f"(d[1]), "+f"(d[2]), "+f"(d[3])
                 : "r"(a0), "r"(a1), "r"(a2), "r"(a3), "r"(b0), "r"(b1));
}
__device__ __forceinline__ void cpa16(uint32_t daddr, const void* gaddr) {
    asm volatile("cp.async.cg.shared.global [%0], [%1], 16;" :: "r"(daddr), "l"(gaddr));
}
__device__ __forceinline__ void cpa_commit() {
    asm volatile("cp.async.commit_group;" ::: "memory");
}
template <int N>
__device__ __forceinline__ void cpa_wait() {
    asm volatile("cp.async.wait_group %0;" :: "n"(N) : "memory");
}

// ---------------------------------------------------------------------------
// Stage 1: grid 2048 = (512 mtiles x 4 p4), 128 thr.
// ---------------------------------------------------------------------------
#define S1_SMEM_W (4352 + 8704)

__global__ __launch_bounds__(128) void ggnn_stage1(const float* __restrict__ h,
                                                   const float* __restrict__ Win,
                                                   const float* __restrict__ Wout) {
    extern __shared__ uint32_t s1[];
    uint32_t* hs = s1;            // [row][e] stride 68
    uint32_t* ws = s1 + 4352;     // [e][n] stride 136

    const int bx = blockIdx.x;
    const int mtile = bx >> 2, p4 = bx & 3;
    const int t = threadIdx.x;
    const int warp = t >> 5, lane = t & 31;
    const int g = lane >> 2, tig = lane & 3;
    const int r0 = warp * 16 + g;

    // stage W' slice: ws[e][n=t] = tf32(W[c][d][e] - (c<3 ? W[3][d][e] : 0))
    {
        const float* Wd = (p4 & 2) ? Wout : Win;
        const int c = 2 * (p4 & 1) + (t >> 6), d = t & 63;
        const float4* src  = (const float4*)(Wd + (size_t)(c * 64 + d) * 64);
        const float4* src3 = (const float4*)(Wd + (size_t)(192 + d) * 64);
        const bool sub = (c != 3);
#pragma unroll
        for (int i = 0; i < 16; i++) {
            float4 v = src[i];
            if (sub) {
                float4 v3 = src3[i];
                v.x -= v3.x; v.y -= v3.y; v.z -= v3.z; v.w -= v3.w;
            }
            int e = 4 * i;
            ws[(e + 0) * 136 + t] = f2tf(v.x);
            ws[(e + 1) * 136 + t] = f2tf(v.y);
            ws[(e + 2) * 136 + t] = f2tf(v.z);
            ws[(e + 3) * 136 + t] = f2tf(v.w);
        }
    }
    const float* hbase = h + (size_t)mtile * 4096;
#pragma unroll
    for (int q = 0; q < 8; q++) {
        int f4 = t + q * 128;
        int row = f4 >> 4, e4 = (f4 & 15) * 4;
        float4 v = *(const float4*)(hbase + row * 64 + e4);
        uint4 u = make_uint4(f2tf(v.x), f2tf(v.y), f2tf(v.z), f2tf(v.w));
        *(uint4*)(hs + row * 68 + e4) = u;
    }
    __syncthreads();

    float acc[16][4];
#pragma unroll
    for (int nt = 0; nt < 16; nt++)
#pragma unroll
        for (int k = 0; k < 4; k++) acc[nt][k] = 0.f;

#pragma unroll
    for (int ks = 0; ks < 8; ks++) {
        int e0 = ks * 8;
        uint32_t a0 = hs[r0 * 68 + e0 + tig];
        uint32_t a1 = hs[(r0 + 8) * 68 + e0 + tig];
        uint32_t a2 = hs[r0 * 68 + e0 + tig + 4];
        uint32_t a3 = hs[(r0 + 8) * 68 + e0 + tig + 4];
#pragma unroll
        for (int nt = 0; nt < 16; nt++) {
            uint32_t b0 = ws[(e0 + tig) * 136 + nt * 8 + g];
            uint32_t b1 = ws[(e0 + tig + 4) * 136 + nt * 8 + g];
            mma8_tf32(acc[nt], a0, a1, a2, a3, b0, b1);
        }
    }

    const int b = mtile >> 4;
    const int ch = (mtile & 15) * 4 + warp;
    const int dir = p4 >> 1, a = p4 & 1;
    uint32_t* blob = g_scratch + (size_t)(b * 2 + dir) * 98304 + ch * 1536;

    if (a == 0) {
        // rows r = g + 8*rb2: word (G'_0, G'_1) at pd = 16tig + 8half + nt
#pragma unroll
        for (int rb2 = 0; rb2 < 2; rb2++) {
            uint32_t* dst = blob + (g + 8 * rb2) * 64 + 16 * tig;
            int i0 = rb2 * 2;
#pragma unroll
            for (int half = 0; half < 2; half++) {
#pragma unroll
                for (int grp = 0; grp < 2; grp++) {
                    uint4 u;
                    u.x = pkh2(acc[grp * 4 + 0][i0 + half], acc[grp * 4 + 8][i0 + half]);
                    u.y = pkh2(acc[grp * 4 + 1][i0 + half], acc[grp * 4 + 9][i0 + half]);
                    u.z = pkh2(acc[grp * 4 + 2][i0 + half], acc[grp * 4 + 10][i0 + half]);
                    u.w = pkh2(acc[grp * 4 + 3][i0 + half], acc[grp * 4 + 11][i0 + half]);
                    *(uint4*)(dst + half * 8 + grp * 4) = u;
                }
            }
        }
    } else {
        // step-2 rows 16..23: pairs of G'_2 across j (shuffle lane g <-> g^4)
        uint32_t w2[2][8];
#pragma unroll
        for (int half = 0; half < 2; half++) {
#pragma unroll
            for (int nt = 0; nt < 8; nt++) {
                float va = acc[nt][half];          // rb2=0: jl = g
                float vb = acc[nt][2 + half];      // rb2=1: jl = g+8
                float oa = __shfl_xor_sync(0xffffffffu, va, 16);
                float ob = __shfl_xor_sync(0xffffffffu, vb, 16);
                w2[half][nt] = (g < 4) ? pkh2(va, oa) : pkh2(ob, vb);
            }
        }
        uint32_t* dst2 = blob + (16 + g) * 64 + 16 * tig;
        *(uint4*)(dst2 + 0)  = make_uint4(w2[0][0], w2[0][1], w2[0][2], w2[0][3]);
        *(uint4*)(dst2 + 4)  = make_uint4(w2[0][4], w2[0][5], w2[0][6], w2[0][7]);
        *(uint4*)(dst2 + 8)  = make_uint4(w2[1][0], w2[1][1], w2[1][2], w2[1][3]);
        *(uint4*)(dst2 + 12) = make_uint4(w2[1][4], w2[1][5], w2[1][6], w2[1][7]);
        // G_3 side buffer: word (d even, d odd) at dw' = 8tig + nt
        uint32_t* g3b = g_g3 + (size_t)(b * 2 + dir) * 32768;
#pragma unroll
        for (int rb2 = 0; rb2 < 2; rb2++) {
            int j = ch * 16 + g + 8 * rb2;
            uint32_t w3[8];
#pragma unroll
            for (int nt = 0; nt < 8; nt++)
                w3[nt] = pkh2(acc[nt + 8][2 * rb2], acc[nt + 8][2 * rb2 + 1]);
            uint32_t* dst3 = g3b + j * 32 + 8 * tig;
            *(uint4*)(dst3 + 0) = make_uint4(w3[0], w3[1], w3[2], w3[3]);
            *(uint4*)(dst3 + 4) = make_uint4(w3[4], w3[5], w3[6], w3[7]);
        }
    }
}

// ---------------------------------------------------------------------------
// g3reduce: R[b2][d] = sum_j G_3[b2][j][d].  grid 64 x 256 thr. Deterministic.
// ---------------------------------------------------------------------------
__global__ void ggnn_g3reduce() {
    const int b2 = blockIdx.x, t = threadIdx.x;
    const int dw = t & 31, jl = t >> 5;
    const uint32_t* src = g_g3 + (size_t)b2 * 32768;
    float s0 = 0.f, s1 = 0.f;
    for (int j = jl; j < 1024; j += 8) {
        __half2 w = *(const __half2*)(src + j * 32 + dw);
        float2 f = __half22float2(w);
        s0 += f.x; s1 += f.y;
    }
    __shared__ float red[8][64];
    red[jl][2 * dw] = s0;
    red[jl][2 * dw + 1] = s1;
    __syncthreads();
    if (t < 64) {
        float v = 0.f;
#pragma unroll
        for (int q = 0; q < 8; q++) v += red[q][t];
        int dw2 = t >> 1, r = t & 1;
        int p = (dw2 & 7) * 4 + (dw2 >> 3);       // un-permute dw' -> d-pair
        g_R[b2 * 64 + 2 * p + r] = v;
    }
}

// ---------------------------------------------------------------------------
// Stage 2: grid (8 mtiles, 2 dirs, 32 b), 128 thr (4 warps x 32 rows), fp16 MMA.
// 2 buffers x (gs 24x68 + adj 2560) = 8384 words = 33.5 KB static smem.
// ---------------------------------------------------------------------------
#define GS2_W (24 * 68)                  // 1632
#define AS2_W 2560
#define BUF2_W (GS2_W + AS2_W)           // 4192
#define SM2_W (2 * BUF2_W)               // 8384 words

__device__ __forceinline__ uint32_t sel2(int v0, int v1) {
    return ((v0 == 2) ? 0x3C00u : 0u) | ((v1 == 2) ? 0x3C000000u : 0u);
}

template <int DIR>
__device__ __forceinline__ void stage2_impl(uint32_t* sm,
                                            const int* __restrict__ adj,
                                            const float* __restrict__ bias,
                                            float* __restrict__ out) {
    const int mtile = blockIdx.x;
    const int b     = blockIdx.z;
    const int t = threadIdx.x;
    const int warp = t >> 5, lane = t & 31;
    const int g = lane >> 2, tig = lane & 3;
    const int mbase = mtile * 128;
    const int rw = warp * 32;

    const uint32_t* blob = g_scratch + (size_t)(b * 2 + DIR) * 98304;
    const int* adjb = adj + (size_t)b * 1048576;

    float acc[2][8][4];
#pragma unroll
    for (int rb = 0; rb < 2; rb++)
#pragma unroll
        for (int nt = 0; nt < 8; nt++)
#pragma unroll
            for (int k = 0; k < 4; k++) acc[rb][nt][k] = 0.f;

    auto issue = [&](int ch, int buf) {
        const int j0 = ch * 16;
        uint32_t gdst = (uint32_t)__cvta_generic_to_shared(sm + buf * BUF2_W);
        uint32_t adst = gdst + GS2_W * 4;
        const uint32_t* gsrc = blob + (size_t)ch * 1536;
#pragma unroll
        for (int q = 0; q < 3; q++) {            // 384 u4s of G
            int idx = t + q * 128;
            int r = idx >> 4, pd4 = (idx & 15) * 4;
            cpa16(gdst + (r * 68 + pd4) * 4, gsrc + r * 64 + pd4);
        }
        if constexpr (DIR == 0) {                // [r][jj] stride 20
#pragma unroll
            for (int q = 0; q < 4; q++) {
                int idx = t + q * 128;
                int r = idx >> 2, c4 = (idx & 3) * 4;
                cpa16(adst + (r * 20 + c4) * 4, adjb + (size_t)(mbase + r) * 1024 + j0 + c4);
            }
        } else {                                 // [jj][r] stride 136
#pragma unroll
            for (int q = 0; q < 4; q++) {
                int idx = t + q * 128;
                int jj = idx >> 5, r4 = (idx & 31) * 4;
                cpa16(adst + (jj * 136 + r4) * 4, adjb + (size_t)(j0 + jj) * 1024 + mbase + r4);
            }
        }
        cpa_commit();
    };

    issue(0, 0);

#pragma unroll 1
    for (int ch = 0; ch < 64; ch++) {
        if (ch < 63) { issue(ch + 1, (ch + 1) & 1); cpa_wait<1>(); }
        else         { cpa_wait<0>(); }
        __syncthreads();

        const uint32_t* gs = sm + (ch & 1) * BUF2_W;
        const int* as_ = (const int*)(gs + GS2_W);
        constexpr int RS = DIR ? 1 : 20;
        constexpr int JS = DIR ? 136 : 1;

        // preload adj: rows rw+g+8*ri, j = tig+4q — serves all 3 steps
        int vv[4][4];
#pragma unroll
        for (int ri = 0; ri < 4; ri++)
#pragma unroll
            for (int q = 0; q < 4; q++)
                vv[ri][q] = as_[(rw + g + 8 * ri) * RS + (tig + 4 * q) * JS];

        // steps 0,1: class pairs (0,1); A = lo32(0x3C00 << 16v)
#pragma unroll
        for (int s = 0; s < 2; s++) {
            uint32_t aw[4][2];
#pragma unroll
            for (int ri = 0; ri < 4; ri++) {
                aw[ri][0] = (uint32_t)(0x3C00ULL << (vv[ri][2 * s] << 4));
                aw[ri][1] = (uint32_t)(0x3C00ULL << (vv[ri][2 * s + 1] << 4));
            }
            const uint32_t* bp0 = gs + (8 * s + tig) * 68 + 8 * g;
            const uint32_t* bp1 = bp0 + 4 * 68;
            uint4 B0a = *(const uint4*)(bp0);
            uint4 B0b = *(const uint4*)(bp0 + 4);
            uint4 B1a = *(const uint4*)(bp1);
            uint4 B1b = *(const uint4*)(bp1 + 4);
#pragma unroll
            for (int rb = 0; rb < 2; rb++) {
                uint32_t a0 = aw[2 * rb][0], a1 = aw[2 * rb + 1][0];
                uint32_t a2 = aw[2 * rb][1], a3 = aw[2 * rb + 1][1];
                mma16_f16(acc[rb][0], a0, a1, a2, a3, B0a.x, B1a.x);
                mma16_f16(acc[rb][1], a0, a1, a2, a3, B0a.y, B1a.y);
                mma16_f16(acc[rb][2], a0, a1, a2, a3, B0a.z, B1a.z);
                mma16_f16(acc[rb][3], a0, a1, a2, a3, B0a.w, B1a.w);
                mma16_f16(acc[rb][4], a0, a1, a2, a3, B0b.x, B1b.x);
                mma16_f16(acc[rb][5], a0, a1, a2, a3, B0b.y, B1b.y);
                mma16_f16(acc[rb][6], a0, a1, a2, a3, B0b.z, B1b.z);
                mma16_f16(acc[rb][7], a0, a1, a2, a3, B0b.w, B1b.w);
            }
        }
        // step 2: class-2 pairs across j
        {
            uint32_t aw[4][2];
#pragma unroll
            for (int ri = 0; ri < 4; ri++) {
                aw[ri][0] = sel2(vv[ri][0], vv[ri][1]);
                aw[ri][1] = sel2(vv[ri][2], vv[ri][3]);
            }
            const uint32_t* bp0 = gs + (16 + tig) * 68 + 8 * g;
            const uint32_t* bp1 = bp0 + 4 * 68;
            uint4 B0a = *(const uint4*)(bp0);
            uint4 B0b = *(const uint4*)(bp0 + 4);
            uint4 B1a = *(const uint4*)(bp1);
            uint4 B1b = *(const uint4*)(bp1 + 4);
#pragma unroll
            for (int rb = 0; rb < 2; rb++) {
                uint32_t a0 = aw[2 * rb][0], a1 = aw[2 * rb + 1][0];
                uint32_t a2 = aw[2 * rb][1], a3 = aw[2 * rb + 1][1];
                mma16_f16(acc[rb][0], a0, a1, a2, a3, B0a.x, B1a.x);
                mma16_f16(acc[rb][1], a0, a1, a2, a3, B0a.y, B1a.y);
                mma16_f16(acc[rb][2], a0, a1, a2, a3, B0a.z, B1a.z);
                mma16_f16(acc[rb][3], a0, a1, a2, a3, B0a.w, B1a.w);
                mma16_f16(acc[rb][4], a0, a1, a2, a3, B0b.x, B1b.x);
                mma16_f16(acc[rb][5], a0, a1, a2, a3, B0b.y, B1b.y);
                mma16_f16(acc[rb][6], a0, a1, a2, a3, B0b.z, B1b.z);
                mma16_f16(acc[rb][7], a0, a1, a2, a3, B0b.w, B1b.w);
            }
        }
        __syncthreads();
    }

    // epilogue: + bias + rank-1 term R
    const float* Rb = g_R + (size_t)(b * 2 + DIR) * 64;
#pragma unroll
    for (int rb = 0; rb < 2; rb++) {
        const int i0 = mbase + rw + rb * 16 + g;
#pragma unroll
        for (int nt = 0; nt < 8; nt++) {
            int nl = nt * 8 + tig * 2;
            int n = DIR * 64 + nl;
            float2 bv = *(const float2*)(bias + n);
            float2 rv = *(const float2*)(Rb + nl);
            float* o0 = out + ((size_t)b * 1024 + i0) * 128 + n;
            float* o1 = out + ((size_t)b * 1024 + i0 + 8) * 128 + n;
            *(float2*)o0 = make_float2(acc[rb][nt][0] + bv.x + rv.x,
                                       acc[rb][nt][1] + bv.y + rv.y);
            *(float2*)o1 = make_float2(acc[rb][nt][2] + bv.x + rv.x,
                                       acc[rb][nt][3] + bv.y + rv.y);
        }
    }
}

__global__ __launch_bounds__(128, 4) void ggnn_stage2(const int* __restrict__ adj,
                                                      const float* __restrict__ bias,
                                                      float* __restrict__ out) {
    __shared__ uint32_t sm[SM2_W];
    if (blockIdx.y == 0) stage2_impl<0>(sm, adj, bias, out);
    else                 stage2_impl<1>(sm, adj, bias, out);
}

extern "C" void kernel_launch(void* const* d_in, const int* in_sizes, int n_in,
                              void* d_out, int out_size) {
    (void)in_sizes; (void)n_in; (void)out_size;
    const float* h    = (const float*)d_in[0];
    const int*   adj  = (const int*)d_in[1];
    const float* Win  = (const float*)d_in[2];
    const float* Wout = (const float*)d_in[3];
    const float* bias = (const float*)d_in[4];
    float* out = (float*)d_out;

    cudaFuncSetAttribute(ggnn_stage1, cudaFuncAttributeMaxDynamicSharedMemorySize,
                         S1_SMEM_W * 4);

    ggnn_stage1<<<2048, 128, S1_SMEM_W * 4>>>(h, Win, Wout);
    ggnn_g3reduce<<<64, 256>>>();
    ggnn_stage2<<<dim3(8, 2, 32), 128>>>(adj, bias, out);
}

// round 16
// speedup vs baseline: 1.2495x; 1.2047x over previous
#include <cuda_runtime.h>
#include <cuda_fp16.h>
#include <cstdint>

// GGNN message passing (SIMT mma.sync).
// Identity: sum_c onehot = 1 exactly => with G'_c=(W_c-W_3)h (c<3), G_3=W_3 h:
//   m = sum_j sum_{c<3} 1[adjX==c]*G'_c[j] + sum_j G_3[j] (rank-1 term R).
// Prep: wt2[p4][kw][n] = f16x2(W'[n][2kw], W'[n][2kw+1]), p4=dir*2+a, n->(c,d).
// Stage1 (fp16 m16n8k16): G' and G_3 from fp16 h x fp16 W', f32 accum. Blob
//   [b2][ch][24][64]: rows 0..15 = (G'_0,G'_1) pairs per j; rows 16..23 =
//   (G'_2[jl=m], G'_2[jl=m+8]) pairs (thread-local, no shuffles); pd=(d&7)*16-ish
//   permutation pd: d = (pd&7)*8 + (pd>>3). G_3 -> side buffer.
// g3reduce: R[b2][d] = sum_j G_3 (deterministic).
// Stage2 (fp16 m16n8k16): K=3072, 64 chunks x 3 k16-steps; one-hot A in regs;
//   step2 pairing (j, j+8). Epilogue adds bias + R.
//   dir=0: adjX=adj[b,i,j]; dir=1: adjX=adj[b,j,i].

__device__ uint32_t g_scratch[(size_t)6291456];  // 24 MB blob
__device__ uint32_t g_g3[(size_t)2097152];       // 8 MB: [b2][j][dw'=8tig+nt]
__device__ float    g_R[4096];                   // [b2][64]
__device__ uint32_t wt2_dev[16384];              // [p4][kw 32][n 128] f16x2

__device__ __forceinline__ uint32_t pkh2(float lo, float hi) {
    __half2 p = __floats2half2_rn(lo, hi); return *(uint32_t*)&p;
}
__device__ __forceinline__ void mma16_f16(float* d, uint32_t a0, uint32_t a1,
                                          uint32_t a2, uint32_t a3, uint32_t b0, uint32_t b1) {
    asm volatile("mma.sync.aligned.m16n8k16.row.col.f32.f16.f16.f32 "
                 "{%0,%1,%2,%3}, {%4,%5,%6,%7}, {%8,%9}, {%0,%1,%2,%3};"
                 : "+f"(d[0]), "+f"(d[1]), "+f"(d[2]), "+f"(d[3])
                 : "r"(a0), "r"(a1), "r"(a2), "r"(a3), "r"(b0), "r"(b1));
}
__device__ __forceinline__ void cpa16(uint32_t daddr, const void* gaddr) {
    asm volatile("cp.async.cg.shared.global [%0], [%1], 16;" :: "r"(daddr), "l"(gaddr));
}
__device__ __forceinline__ void cpa_commit() {
    asm volatile("cp.async.commit_group;" ::: "memory");
}
template <int N>
__device__ __forceinline__ void cpa_wait() {
    asm volatile("cp.async.wait_group %0;" :: "n"(N) : "memory");
}

// ---------------------------------------------------------------------------
// Prep: wt2[p4][kw][n] = f16x2 of W' along e. grid 64 x 256 thr.
// ---------------------------------------------------------------------------
__global__ void ggnn_prep(const float* __restrict__ Win, const float* __restrict__ Wout) {
    int idx = blockIdx.x * 256 + threadIdx.x;    // 0..16383
    int p4 = idx >> 12, kw = (idx >> 7) & 31, n = idx & 127;
    int dir = p4 >> 1, a = p4 & 1;
    int c = 2 * a + (n >> 6), d = n & 63;
    const float* Wd = dir ? Wout : Win;
    int e0 = 2 * kw;
    float v0 = Wd[(c * 64 + d) * 64 + e0];
    float v1 = Wd[(c * 64 + d) * 64 + e0 + 1];
    if (c != 3) {
        v0 -= Wd[(192 + d) * 64 + e0];
        v1 -= Wd[(192 + d) * 64 + e0 + 1];
    }
    wt2_dev[p4 * 4096 + kw * 128 + n] = pkh2(v0, v1);
}

// ---------------------------------------------------------------------------
// Stage 1: grid 2048 = (512 mtiles x 4 p4), 128 thr, fp16 m16n8k16.
// smem: hs[64*36] (f16x2, [row][kw]) + ws[32*132] ([kw][n]) = 26.1 KB static.
// ---------------------------------------------------------------------------
__global__ __launch_bounds__(128) void ggnn_stage1(const float* __restrict__ h) {
    __shared__ uint32_t hs[64 * 36];
    __shared__ uint32_t ws[32 * 132];

    const int bx = blockIdx.x;
    const int mtile = bx >> 2, p4 = bx & 3;
    const int t = threadIdx.x;
    const int warp = t >> 5, lane = t & 31;
    const int g = lane >> 2, tig = lane & 3;
    const int r0 = warp * 16 + g;

    // stage W' slice via cp.async (16 KB)
    {
        uint32_t dst = (uint32_t)__cvta_generic_to_shared(ws);
        const uint32_t* src = wt2_dev + p4 * 4096;
#pragma unroll
        for (int q = 0; q < 8; q++) {
            int idx = t + q * 128;               // 1024 u4s
            int kw = idx >> 5, n4 = (idx & 31) * 4;
            cpa16(dst + (kw * 132 + n4) * 4, src + kw * 128 + n4);
        }
        cpa_commit();
    }
    // stage h tile as f16x2
    const float* hbase = h + (size_t)mtile * 4096;
#pragma unroll
    for (int q = 0; q < 8; q++) {
        int f4 = t + q * 128;
        int row = f4 >> 4, w2 = (f4 & 15) * 2;
        float4 v = *(const float4*)(hbase + row * 64 + w2 * 2);
        *(uint2*)(hs + row * 36 + w2) = make_uint2(pkh2(v.x, v.y), pkh2(v.z, v.w));
    }
    cpa_wait<0>();
    __syncthreads();

    float acc[16][4];
#pragma unroll
    for (int nt = 0; nt < 16; nt++)
#pragma unroll
        for (int k = 0; k < 4; k++) acc[nt][k] = 0.f;

#pragma unroll
    for (int s = 0; s < 4; s++) {
        uint32_t a0 = hs[r0 * 36 + 8 * s + tig];
        uint32_t a1 = hs[(r0 + 8) * 36 + 8 * s + tig];
        uint32_t a2 = hs[r0 * 36 + 8 * s + tig + 4];
        uint32_t a3 = hs[(r0 + 8) * 36 + 8 * s + tig + 4];
#pragma unroll
        for (int nt = 0; nt < 16; nt++) {
            uint32_t b0 = ws[(8 * s + tig) * 132 + nt * 8 + g];
            uint32_t b1 = ws[(8 * s + tig + 4) * 132 + nt * 8 + g];
            mma16_f16(acc[nt], a0, a1, a2, a3, b0, b1);
        }
    }

    const int b = mtile >> 4;
    const int ch = (mtile & 15) * 4 + warp;
    const int dir = p4 >> 1, a = p4 & 1;
    uint32_t* blob = g_scratch + (size_t)(b * 2 + dir) * 98304 + ch * 1536;

    if (a == 0) {
        // rows jl = g + 8*rb2: word (G'_0[d], G'_1[d]) at pd
#pragma unroll
        for (int rb2 = 0; rb2 < 2; rb2++) {
            uint32_t* dst = blob + (g + 8 * rb2) * 64 + 16 * tig;
            int i0 = rb2 * 2;
#pragma unroll
            for (int half = 0; half < 2; half++) {
#pragma unroll
                for (int grp = 0; grp < 2; grp++) {
                    uint4 u;
                    u.x = pkh2(acc[grp * 4 + 0][i0 + half], acc[grp * 4 + 8][i0 + half]);
                    u.y = pkh2(acc[grp * 4 + 1][i0 + half], acc[grp * 4 + 9][i0 + half]);
                    u.z = pkh2(acc[grp * 4 + 2][i0 + half], acc[grp * 4 + 10][i0 + half]);
                    u.w = pkh2(acc[grp * 4 + 3][i0 + half], acc[grp * 4 + 11][i0 + half]);
                    *(uint4*)(dst + half * 8 + grp * 4) = u;
                }
            }
        }
    } else {
        // step-2 rows 16+g: word (G'_2[jl=g][d], G'_2[jl=g+8][d]) — thread-local
        uint32_t* dst2 = blob + (16 + g) * 64 + 16 * tig;
#pragma unroll
        for (int half = 0; half < 2; half++) {
#pragma unroll
            for (int grp = 0; grp < 2; grp++) {
                uint4 u;
                u.x = pkh2(acc[grp * 4 + 0][half], acc[grp * 4 + 0][2 + half]);
                u.y = pkh2(acc[grp * 4 + 1][half], acc[grp * 4 + 1][2 + half]);
                u.z = pkh2(acc[grp * 4 + 2][half], acc[grp * 4 + 2][2 + half]);
                u.w = pkh2(acc[grp * 4 + 3][half], acc[grp * 4 + 3][2 + half]);
                *(uint4*)(dst2 + half * 8 + grp * 4) = u;
            }
        }
        // G_3 side buffer: word (d even, d odd) at dw' = 8tig + nt
        uint32_t* g3b = g_g3 + (size_t)(b * 2 + dir) * 32768;
#pragma unroll
        for (int rb2 = 0; rb2 < 2; rb2++) {
            int j = ch * 16 + g + 8 * rb2;
            uint32_t w3[8];
#pragma unroll
            for (int nt = 0; nt < 8; nt++)
                w3[nt] = pkh2(acc[nt + 8][2 * rb2], acc[nt + 8][2 * rb2 + 1]);
            uint32_t* dst3 = g3b + j * 32 + 8 * tig;
            *(uint4*)(dst3 + 0) = make_uint4(w3[0], w3[1], w3[2], w3[3]);
            *(uint4*)(dst3 + 4) = make_uint4(w3[4], w3[5], w3[6], w3[7]);
        }
    }
}

// ---------------------------------------------------------------------------
// g3reduce: R[b2][d] = sum_j G_3[b2][j][d]. grid 64 x 256 thr. Deterministic.
// ---------------------------------------------------------------------------
__global__ void ggnn_g3reduce() {
    const int b2 = blockIdx.x, t = threadIdx.x;
    const int dw = t & 31, jl = t >> 5;
    const uint32_t* src = g_g3 + (size_t)b2 * 32768;
    float s0 = 0.f, s1 = 0.f;
    for (int j = jl; j < 1024; j += 8) {
        __half2 w = *(const __half2*)(src + j * 32 + dw);
        float2 f = __half22float2(w);
        s0 += f.x; s1 += f.y;
    }
    __shared__ float red[8][64];
    red[jl][2 * dw] = s0;
    red[jl][2 * dw + 1] = s1;
    __syncthreads();
    if (t < 64) {
        float v = 0.f;
#pragma unroll
        for (int q = 0; q < 8; q++) v += red[q][t];
        int dw2 = t >> 1, r = t & 1;
        int p = (dw2 & 7) * 4 + (dw2 >> 3);      // un-permute dw' -> d-pair
        g_R[b2 * 64 + 2 * p + r] = v;
    }
}

// ---------------------------------------------------------------------------
// Stage 2: grid (8 mtiles, 2 dirs, 32 b), 128 thr (4 warps x 32 rows), fp16 MMA.
// 2 buffers x (gs 24x68 + adj 2560) = 8384 words = 33.5 KB static smem.
// ---------------------------------------------------------------------------
#define GS2_W (24 * 68)                  // 1632
#define AS2_W 2560
#define BUF2_W (GS2_W + AS2_W)           // 4192
#define SM2_W (2 * BUF2_W)               // 8384 words

__device__ __forceinline__ uint32_t sel2(int v0, int v1) {
    return ((v0 == 2) ? 0x3C00u : 0u) | ((v1 == 2) ? 0x3C000000u : 0u);
}

template <int DIR>
__device__ __forceinline__ void stage2_impl(uint32_t* sm,
                                            const int* __restrict__ adj,
                                            const float* __restrict__ bias,
                                            float* __restrict__ out) {
    const int mtile = blockIdx.x;
    const int b     = blockIdx.z;
    const int t = threadIdx.x;
    const int warp = t >> 5, lane = t & 31;
    const int g = lane >> 2, tig = lane & 3;
    const int mbase = mtile * 128;
    const int rw = warp * 32;

    const uint32_t* blob = g_scratch + (size_t)(b * 2 + DIR) * 98304;
    const int* adjb = adj + (size_t)b * 1048576;

    float acc[2][8][4];
#pragma unroll
    for (int rb = 0; rb < 2; rb++)
#pragma unroll
        for (int nt = 0; nt < 8; nt++)
#pragma unroll
            for (int k = 0; k < 4; k++) acc[rb][nt][k] = 0.f;

    auto issue = [&](int ch, int buf) {
        const int j0 = ch * 16;
        uint32_t gdst = (uint32_t)__cvta_generic_to_shared(sm + buf * BUF2_W);
        uint32_t adst = gdst + GS2_W * 4;
        const uint32_t* gsrc = blob + (size_t)ch * 1536;
#pragma unroll
        for (int q = 0; q < 3; q++) {            // 384 u4s of G
            int idx = t + q * 128;
            int r = idx >> 4, pd4 = (idx & 15) * 4;
            cpa16(gdst + (r * 68 + pd4) * 4, gsrc + r * 64 + pd4);
        }
        if constexpr (DIR == 0) {                // [r][jj] stride 20
#pragma unroll
            for (int q = 0; q < 4; q++) {
                int idx = t + q * 128;
                int r = idx >> 2, c4 = (idx & 3) * 4;
                cpa16(adst + (r * 20 + c4) * 4, adjb + (size_t)(mbase + r) * 1024 + j0 + c4);
            }
        } else {                                 // [jj][r] stride 136
#pragma unroll
            for (int q = 0; q < 4; q++) {
                int idx = t + q * 128;
                int jj = idx >> 5, r4 = (idx & 31) * 4;
                cpa16(adst + (jj * 136 + r4) * 4, adjb + (size_t)(j0 + jj) * 1024 + mbase + r4);
            }
        }
        cpa_commit();
    };

    issue(0, 0);

#pragma unroll 1
    for (int ch = 0; ch < 64; ch++) {
        if (ch < 63) { issue(ch + 1, (ch + 1) & 1); cpa_wait<1>(); }
        else         { cpa_wait<0>(); }
        __syncthreads();

        const uint32_t* gs = sm + (ch & 1) * BUF2_W;
        const int* as_ = (const int*)(gs + GS2_W);
        constexpr int RS = DIR ? 1 : 20;
        constexpr int JS = DIR ? 136 : 1;

        // preload adj: rows rw+g+8*ri, j = tig+4q — serves all 3 steps
        int vv[4][4];
#pragma unroll
        for (int ri = 0; ri < 4; ri++)
#pragma unroll
            for (int q = 0; q < 4; q++)
                vv[ri][q] = as_[(rw + g + 8 * ri) * RS + (tig + 4 * q) * JS];

        // steps 0,1: class pairs (0,1); A = lo32(0x3C00 << 16v)
#pragma unroll
        for (int s = 0; s < 2; s++) {
            uint32_t aw[4][2];
#pragma unroll
            for (int ri = 0; ri < 4; ri++) {
                aw[ri][0] = (uint32_t)(0x3C00ULL << (vv[ri][2 * s] << 4));
                aw[ri][1] = (uint32_t)(0x3C00ULL << (vv[ri][2 * s + 1] << 4));
            }
            const uint32_t* bp0 = gs + (8 * s + tig) * 68 + 8 * g;
            const uint32_t* bp1 = bp0 + 4 * 68;
            uint4 B0a = *(const uint4*)(bp0);
            uint4 B0b = *(const uint4*)(bp0 + 4);
            uint4 B1a = *(const uint4*)(bp1);
            uint4 B1b = *(const uint4*)(bp1 + 4);
#pragma unroll
            for (int rb = 0; rb < 2; rb++) {
                uint32_t a0 = aw[2 * rb][0], a1 = aw[2 * rb + 1][0];
                uint32_t a2 = aw[2 * rb][1], a3 = aw[2 * rb + 1][1];
                mma16_f16(acc[rb][0], a0, a1, a2, a3, B0a.x, B1a.x);
                mma16_f16(acc[rb][1], a0, a1, a2, a3, B0a.y, B1a.y);
                mma16_f16(acc[rb][2], a0, a1, a2, a3, B0a.z, B1a.z);
                mma16_f16(acc[rb][3], a0, a1, a2, a3, B0a.w, B1a.w);
                mma16_f16(acc[rb][4], a0, a1, a2, a3, B0b.x, B1b.x);
                mma16_f16(acc[rb][5], a0, a1, a2, a3, B0b.y, B1b.y);
                mma16_f16(acc[rb][6], a0, a1, a2, a3, B0b.z, B1b.z);
                mma16_f16(acc[rb][7], a0, a1, a2, a3, B0b.w, B1b.w);
            }
        }
        // step 2: class-2 pairs (j, j+8) — matches thread-local blob packing
        {
            uint32_t aw[4][2];
#pragma unroll
            for (int ri = 0; ri < 4; ri++) {
                aw[ri][0] = sel2(vv[ri][0], vv[ri][2]);
                aw[ri][1] = sel2(vv[ri][1], vv[ri][3]);
            }
            const uint32_t* bp0 = gs + (16 + tig) * 68 + 8 * g;
            const uint32_t* bp1 = bp0 + 4 * 68;
            uint4 B0a = *(const uint4*)(bp0);
            uint4 B0b = *(const uint4*)(bp0 + 4);
            uint4 B1a = *(const uint4*)(bp1);
            uint4 B1b = *(const uint4*)(bp1 + 4);
#pragma unroll
            for (int rb = 0; rb < 2; rb++) {
                uint32_t a0 = aw[2 * rb][0], a1 = aw[2 * rb + 1][0];
                uint32_t a2 = aw[2 * rb][1], a3 = aw[2 * rb + 1][1];
                mma16_f16(acc[rb][0], a0, a1, a2, a3, B0a.x, B1a.x);
                mma16_f16(acc[rb][1], a0, a1, a2, a3, B0a.y, B1a.y);
                mma16_f16(acc[rb][2], a0, a1, a2, a3, B0a.z, B1a.z);
                mma16_f16(acc[rb][3], a0, a1, a2, a3, B0a.w, B1a.w);
                mma16_f16(acc[rb][4], a0, a1, a2, a3, B0b.x, B1b.x);
                mma16_f16(acc[rb][5], a0, a1, a2, a3, B0b.y, B1b.y);
                mma16_f16(acc[rb][6], a0, a1, a2, a3, B0b.z, B1b.z);
                mma16_f16(acc[rb][7], a0, a1, a2, a3, B0b.w, B1b.w);
            }
        }
        __syncthreads();
    }

    // epilogue: + bias + rank-1 term R
    const float* Rb = g_R + (size_t)(b * 2 + DIR) * 64;
#pragma unroll
    for (int rb = 0; rb < 2; rb++) {
        const int i0 = mbase + rw + rb * 16 + g;
#pragma unroll
        for (int nt = 0; nt < 8; nt++) {
            int nl = nt * 8 + tig * 2;
            int n = DIR * 64 + nl;
            float2 bv = *(const float2*)(bias + n);
            float2 rv = *(const float2*)(Rb + nl);
            float* o0 = out + ((size_t)b * 1024 + i0) * 128 + n;
            float* o1 = out + ((size_t)b * 1024 + i0 + 8) * 128 + n;
            *(float2*)o0 = make_float2(acc[rb][nt][0] + bv.x + rv.x,
                                       acc[rb][nt][1] + bv.y + rv.y);
            *(float2*)o1 = make_float2(acc[rb][nt][2] + bv.x + rv.x,
                                       acc[rb][nt][3] + bv.y + rv.y);
        }
    }
}

__global__ __launch_bounds__(128, 4) void ggnn_stage2(const int* __restrict__ adj,
                                                      const float* __restrict__ bias,
                                                      float* __restrict__ out) {
    __shared__ uint32_t sm[SM2_W];
    if (blockIdx.y == 0) stage2_impl<0>(sm, adj, bias, out);
    else                 stage2_impl<1>(sm, adj, bias, out);
}

extern "C" void kernel_launch(void* const* d_in, const int* in_sizes, int n_in,
                              void* d_out, int out_size) {
    (void)in_sizes; (void)n_in; (void)out_size;
    const float* h    = (const float*)d_in[0];
    const int*   adj  = (const int*)d_in[1];
    const float* Win  = (const float*)d_in[2];
    const float* Wout = (const float*)d_in[3];
    const float* bias = (const float*)d_in[4];
    float* out = (float*)d_out;

    ggnn_prep<<<64, 256>>>(Win, Wout);
    ggnn_stage1<<<2048, 128>>>(h);
    ggnn_g3reduce<<<64, 256>>>();
    ggnn_stage2<<<dim3(8, 2, 32), 128>>>(adj, bias, out);
}